// round 6
// baseline (speedup 1.0000x reference)
#include <cuda_runtime.h>
#include <cuda_fp16.h>
#include <math.h>

#define NNODES 100000
#define KNB 16

// Scratch (bss, no allocation). h reused by both layers (sequential stream).
__device__ __align__(16) __half g_h[NNODES * 64];
__device__ __align__(16) float  g_x1[NNODES * 64];
__device__ float g_sd[NNODES];
__device__ float g_ss[NNODES];

// ---- packed f32x2 helpers --------------------------------------------------
__device__ __forceinline__ unsigned long long pack2(float v) {
    unsigned long long r;
    asm("mov.b64 %0, {%1, %1};" : "=l"(r) : "f"(v));
    return r;
}
__device__ __forceinline__ void ffma2(unsigned long long& d,
                                      unsigned long long a,
                                      unsigned long long b) {
    asm("fma.rn.f32x2 %0, %1, %2, %0;" : "+l"(d) : "l"(a), "l"(b));
}
__device__ __forceinline__ float2 unpack2(unsigned long long v) {
    float2 f;
    asm("mov.b64 {%0, %1}, %2;" : "=f"(f.x), "=f"(f.y) : "l"(v));
    return f;
}

// ---------------------------------------------------------------------------
// GEMM h = x @ W (KD inner, 64 cols) + fused attention dots
//   sd[i] = h[i].a[0:64], ss[i] = h[i].a[64:128];  h stored fp16.
// Tile: 128 rows x 64 cols, 256 threads, 8x4 outputs/thread as 16 f32x2
// accumulators (column pairs). k unrolled by 2:
//   per 2k per thread: 2 LDS.128 (W) + 8 LDS.64 (x, broadcast) + 16 ALU packs
//   + 32 FFMA2  ->  issue:fma = 58:64 fma-pipe-cycles -> FFMA2-pipe bound.
// ---------------------------------------------------------------------------
template <int KD>
__global__ void __launch_bounds__(256) gemm_att_kernel(
    const float* __restrict__ x, const float* __restrict__ W,
    const float* __restrict__ a, __half* __restrict__ h,
    float* __restrict__ sd, float* __restrict__ ss)
{
    extern __shared__ float smem[];
    float* Ws = smem;              // KD x 64
    float* xs = smem + KD * 64;    // 128 x KD row-major

    const int tid = threadIdx.x;
    const int rowbase = blockIdx.x * 128;

    {
        const float4* Wg = reinterpret_cast<const float4*>(W);
        float4* Wv = reinterpret_cast<float4*>(Ws);
        #pragma unroll
        for (int i = tid; i < KD * 16; i += 256) Wv[i] = Wg[i];
    }
    {
        const float4* xg = reinterpret_cast<const float4*>(x + (size_t)rowbase * KD);
        float4* xv = reinterpret_cast<float4*>(xs);
        const int tot = 128 * KD / 4;
        const int nvalid_rows = NNODES - rowbase;
        const int validv = (nvalid_rows >= 128) ? tot : nvalid_rows * (KD / 4);
        for (int i = tid; i < tot; i += 256)
            xv[i] = (i < validv) ? xg[i] : make_float4(0.f, 0.f, 0.f, 0.f);
    }
    __syncthreads();

    const int tx = tid & 15;       // cols tx*4 .. tx*4+3
    const int ty = tid >> 4;       // rows ty*8 .. ty*8+7

    unsigned long long acc[8][2];
    #pragma unroll
    for (int r = 0; r < 8; r++) { acc[r][0] = 0ull; acc[r][1] = 0ull; }

    const float* xr = &xs[ty * 8 * KD];

    #pragma unroll 4
    for (int k = 0; k < KD; k += 2) {
        const ulonglong2 w0 =
            *reinterpret_cast<const ulonglong2*>(&Ws[k * 64 + tx * 4]);
        const ulonglong2 w1 =
            *reinterpret_cast<const ulonglong2*>(&Ws[(k + 1) * 64 + tx * 4]);
        #pragma unroll
        for (int r = 0; r < 8; r++) {
            const float2 xv = *reinterpret_cast<const float2*>(&xr[r * KD + k]);
            const unsigned long long p0 = pack2(xv.x);
            const unsigned long long p1 = pack2(xv.y);
            ffma2(acc[r][0], p0, w0.x);
            ffma2(acc[r][1], p0, w0.y);
            ffma2(acc[r][0], p1, w1.x);
            ffma2(acc[r][1], p1, w1.y);
        }
    }

    const float4 aa = *reinterpret_cast<const float4*>(&a[tx * 4]);
    const float4 ab = *reinterpret_cast<const float4*>(&a[64 + tx * 4]);

    #pragma unroll
    for (int r = 0; r < 8; r++) {
        const int row = rowbase + ty * 8 + r;
        const float2 c01 = unpack2(acc[r][0]);
        const float2 c23 = unpack2(acc[r][1]);
        float pd = c01.x * aa.x + c01.y * aa.y + c23.x * aa.z + c23.y * aa.w;
        float ps = c01.x * ab.x + c01.y * ab.y + c23.x * ab.z + c23.y * ab.w;
        #pragma unroll
        for (int off = 8; off >= 1; off >>= 1) {
            pd += __shfl_xor_sync(0xffffffffu, pd, off);
            ps += __shfl_xor_sync(0xffffffffu, ps, off);
        }
        if (row < NNODES) {
            if (tx == 0) { sd[row] = pd; ss[row] = ps; }
            const __half2 ha = __floats2half2_rn(c01.x, c01.y);
            const __half2 hb = __floats2half2_rn(c23.x, c23.y);
            uint2 uv;
            uv.x = *reinterpret_cast<const unsigned*>(&ha);
            uv.y = *reinterpret_cast<const unsigned*>(&hb);
            *reinterpret_cast<uint2*>(&h[(size_t)row * 64 + tx * 4]) = uv;
        }
    }
}

// ---------------------------------------------------------------------------
// Attention softmax (K=16) + fp16 gather aggregation + bias + relu.
// One warp per node; each lane owns 2 cols as half2 -> one 128B line per
// neighbor row per warp.
// ---------------------------------------------------------------------------
__global__ void __launch_bounds__(256) agg_kernel(
    const __half2* __restrict__ hh, const int* __restrict__ ecol,
    const float* __restrict__ sd, const float* __restrict__ ss,
    const float* __restrict__ b, float2* __restrict__ out)
{
    const int node = (blockIdx.x * blockDim.x + threadIdx.x) >> 5;
    const int lane = threadIdx.x & 31;

    int   col = 0;
    float att;
    if (lane < KNB) {
        col = ecol[node * KNB + lane];
        float ev = sd[node] + ss[col];
        att = (ev > 0.0f) ? ev : 0.2f * ev;     // leaky_relu slope 0.2
    } else {
        att = -1e30f;
    }

    float m = att;
    #pragma unroll
    for (int off = 8; off >= 1; off >>= 1)
        m = fmaxf(m, __shfl_xor_sync(0xffffffffu, m, off));
    const float ex = (lane < KNB) ? __expf(att - m) : 0.0f;
    float s = ex;
    #pragma unroll
    for (int off = 8; off >= 1; off >>= 1)
        s += __shfl_xor_sync(0xffffffffu, s, off);
    att = ex / s;                                // valid in lanes 0..15

    float2 acc = make_float2(0.f, 0.f);
    #pragma unroll
    for (int k = 0; k < KNB; k++) {
        const int   ck = __shfl_sync(0xffffffffu, col, k);
        const float ak = __shfl_sync(0xffffffffu, att, k);
        const float2 hv = __half22float2(hh[(size_t)ck * 32 + lane]);
        acc.x = fmaf(ak, hv.x, acc.x);
        acc.y = fmaf(ak, hv.y, acc.y);
    }

    const float2 bv = reinterpret_cast<const float2*>(b)[lane];
    acc.x = fmaxf(acc.x + bv.x, 0.0f);
    acc.y = fmaxf(acc.y + bv.y, 0.0f);
    out[(size_t)node * 32 + lane] = acc;
}

// ---------------------------------------------------------------------------
extern "C" void kernel_launch(void* const* d_in, const int* in_sizes, int n_in,
                              void* d_out, int out_size)
{
    const float* x    = (const float*)d_in[0];
    // d_in[1] = edge_row: exactly K per node, row-sorted -> implicit, unused
    const int*   ecol = (const int*)d_in[2];
    const float* W1   = (const float*)d_in[3];
    const float* a1   = (const float*)d_in[4];
    const float* b1   = (const float*)d_in[5];
    const float* W2   = (const float*)d_in[6];
    const float* a2   = (const float*)d_in[7];
    const float* b2   = (const float*)d_in[8];

    __half* h;  float *x1, *sd, *ss;
    cudaGetSymbolAddress((void**)&h,  g_h);
    cudaGetSymbolAddress((void**)&x1, g_x1);
    cudaGetSymbolAddress((void**)&sd, g_sd);
    cudaGetSymbolAddress((void**)&ss, g_ss);

    const int smem1 = (128 * 64 + 128 * 128) * 4;   // 96 KB
    const int smem2 = (64 * 64 + 128 * 64) * 4;     // 48 KB
    cudaFuncSetAttribute(gemm_att_kernel<128>,
                         cudaFuncAttributeMaxDynamicSharedMemorySize, smem1);
    cudaFuncSetAttribute(gemm_att_kernel<64>,
                         cudaFuncAttributeMaxDynamicSharedMemorySize, smem2);

    const int gemm_blocks = (NNODES + 127) / 128;   // 782
    const int agg_blocks  = NNODES / 8;             // 12500

    // Layer 1
    gemm_att_kernel<128><<<gemm_blocks, 256, smem1>>>(x, W1, a1, h, sd, ss);
    agg_kernel<<<agg_blocks, 256>>>((const __half2*)h, ecol, sd, ss, b1,
                                    (float2*)x1);
    // Layer 2
    gemm_att_kernel<64><<<gemm_blocks, 256, smem2>>>(x1, W2, a2, h, sd, ss);
    agg_kernel<<<agg_blocks, 256>>>((const __half2*)h, ecol, sd, ss, b2,
                                    (float2*)d_out);
}

// round 7
// speedup vs baseline: 1.1416x; 1.1416x over previous
#include <cuda_runtime.h>
#include <cuda_fp16.h>
#include <math.h>

#define NNODES 100000
#define KNB 16

// Scratch (bss, no allocation). h reused by both layers (sequential stream).
__device__ __align__(16) __half g_h[NNODES * 64];
__device__ __align__(16) float  g_x1[NNODES * 64];
__device__ float g_sd[NNODES];
__device__ float g_ss[NNODES];

// ---- tf32 helpers ----------------------------------------------------------
__device__ __forceinline__ unsigned cvt_tf32(float f) {
    unsigned u;
    asm("cvt.rna.tf32.f32 %0, %1;" : "=r"(u) : "f"(f));
    return u;
}
__device__ __forceinline__ void mma_tf32(float* c,
    unsigned a0, unsigned a1, unsigned a2, unsigned a3,
    unsigned b0, unsigned b1)
{
    asm volatile(
        "mma.sync.aligned.m16n8k8.row.col.f32.tf32.tf32.f32 "
        "{%0,%1,%2,%3}, {%4,%5,%6,%7}, {%8,%9}, {%0,%1,%2,%3};"
        : "+f"(c[0]), "+f"(c[1]), "+f"(c[2]), "+f"(c[3])
        : "r"(a0), "r"(a1), "r"(a2), "r"(a3), "r"(b0), "r"(b1));
}

// ---------------------------------------------------------------------------
// GEMM h = x @ W (KD inner, 64 cols) on tf32 tensor cores + fused attention
// dots sd[i]=h[i].a[0:64], ss[i]=h[i].a[64:128]; h stored fp16.
// Block: 256 threads (8 warps), tile 128 rows x 64 cols; warp w owns rows
// 16w..16w+15, all 64 cols (8 n-tiles of m16n8k8). Tiles converted to tf32
// at smem fill. Padded strides -> all fragment LDS conflict-free:
//   xs stride KD+4 : bank = (4r+k)%32, distinct per instruction
//   Ws stride 72   : bank = (8k+n)%32, distinct per instruction
// ---------------------------------------------------------------------------
template <int KD>
__global__ void __launch_bounds__(256) gemm_mma_kernel(
    const float* __restrict__ x, const float* __restrict__ W,
    const float* __restrict__ a, __half* __restrict__ h,
    float* __restrict__ sd, float* __restrict__ ss)
{
    constexpr int XS = KD + 4;   // padded x row stride (u32 units)
    constexpr int WS = 72;       // padded W row stride (u32 units)
    extern __shared__ unsigned smem_u[];
    unsigned* Wsu = smem_u;               // KD x WS
    unsigned* xsu = smem_u + KD * WS;     // 128 x XS

    const int tid  = threadIdx.x;
    const int warp = tid >> 5;
    const int lane = tid & 31;
    const int q = lane & 3;      // quad lane
    const int g = lane >> 2;     // group id
    const int rowbase = blockIdx.x * 128;

    // Fill W tile (tf32 bits, STS.128)
    {
        const float4* Wg = reinterpret_cast<const float4*>(W);
        #pragma unroll
        for (int i = tid; i < KD * 16; i += 256) {
            const float4 v = Wg[i];
            const int k = i >> 4, n4 = i & 15;
            uint4 u;
            u.x = cvt_tf32(v.x); u.y = cvt_tf32(v.y);
            u.z = cvt_tf32(v.z); u.w = cvt_tf32(v.w);
            *reinterpret_cast<uint4*>(&Wsu[k * WS + n4 * 4]) = u;
        }
    }
    // Fill x tile (tf32 bits, zero-pad rows past NNODES)
    {
        const float4* xg = reinterpret_cast<const float4*>(x + (size_t)rowbase * KD);
        constexpr int K4 = KD / 4;
        const int tot = 128 * K4;
        const int nvr = NNODES - rowbase;
        const int validv = (nvr >= 128) ? tot : nvr * K4;
        for (int i = tid; i < tot; i += 256) {
            const float4 v = (i < validv) ? xg[i] : make_float4(0.f, 0.f, 0.f, 0.f);
            const int r = i / K4, k4 = i % K4;
            uint4 u;
            u.x = cvt_tf32(v.x); u.y = cvt_tf32(v.y);
            u.z = cvt_tf32(v.z); u.w = cvt_tf32(v.w);
            *reinterpret_cast<uint4*>(&xsu[r * XS + k4 * 4]) = u;
        }
    }
    __syncthreads();

    float acc[8][4];
    #pragma unroll
    for (int nt = 0; nt < 8; nt++)
        #pragma unroll
        for (int j = 0; j < 4; j++) acc[nt][j] = 0.0f;

    const unsigned* xw = &xsu[(warp * 16) * XS];

    #pragma unroll
    for (int k0 = 0; k0 < KD; k0 += 8) {
        const unsigned a0 = xw[g * XS + k0 + q];
        const unsigned a1 = xw[(g + 8) * XS + k0 + q];
        const unsigned a2 = xw[g * XS + k0 + q + 4];
        const unsigned a3 = xw[(g + 8) * XS + k0 + q + 4];
        #pragma unroll
        for (int nt = 0; nt < 8; nt++) {
            const unsigned b0 = Wsu[(k0 + q) * WS + nt * 8 + g];
            const unsigned b1 = Wsu[(k0 + q + 4) * WS + nt * 8 + g];
            mma_tf32(acc[nt], a0, a1, a2, a3, b0, b1);
        }
    }

    // Fused attention dots on fp32 accumulators.
    // Thread owns rows (16w+g, 16w+g+8), cols {8nt+2q, 8nt+2q+1}.
    float pd0 = 0.f, ps0 = 0.f, pd1 = 0.f, ps1 = 0.f;
    #pragma unroll
    for (int nt = 0; nt < 8; nt++) {
        const float2 av = reinterpret_cast<const float2*>(a)[nt * 4 + q];
        const float2 bv = reinterpret_cast<const float2*>(a + 64)[nt * 4 + q];
        pd0 += acc[nt][0] * av.x + acc[nt][1] * av.y;
        ps0 += acc[nt][0] * bv.x + acc[nt][1] * bv.y;
        pd1 += acc[nt][2] * av.x + acc[nt][3] * av.y;
        ps1 += acc[nt][2] * bv.x + acc[nt][3] * bv.y;
    }
    #pragma unroll
    for (int off = 2; off >= 1; off >>= 1) {
        pd0 += __shfl_xor_sync(0xffffffffu, pd0, off);
        ps0 += __shfl_xor_sync(0xffffffffu, ps0, off);
        pd1 += __shfl_xor_sync(0xffffffffu, pd1, off);
        ps1 += __shfl_xor_sync(0xffffffffu, ps1, off);
    }

    const int row0 = rowbase + warp * 16 + g;
    const int row1 = row0 + 8;
    if (q == 0) {
        if (row0 < NNODES) { sd[row0] = pd0; ss[row0] = ps0; }
        if (row1 < NNODES) { sd[row1] = pd1; ss[row1] = ps1; }
    }

    if (row0 < NNODES) {
        #pragma unroll
        for (int nt = 0; nt < 8; nt++) {
            const __half2 hv = __floats2half2_rn(acc[nt][0], acc[nt][1]);
            *reinterpret_cast<__half2*>(&h[(size_t)row0 * 64 + nt * 8 + 2 * q]) = hv;
        }
    }
    if (row1 < NNODES) {
        #pragma unroll
        for (int nt = 0; nt < 8; nt++) {
            const __half2 hv = __floats2half2_rn(acc[nt][2], acc[nt][3]);
            *reinterpret_cast<__half2*>(&h[(size_t)row1 * 64 + nt * 8 + 2 * q]) = hv;
        }
    }
}

// ---------------------------------------------------------------------------
// Attention softmax (K=16) + fp16 gather aggregation + bias + relu.
// One warp per node; each lane owns 2 cols as half2 -> one 128B line per
// neighbor row per warp.
// ---------------------------------------------------------------------------
__global__ void __launch_bounds__(256) agg_kernel(
    const __half2* __restrict__ hh, const int* __restrict__ ecol,
    const float* __restrict__ sd, const float* __restrict__ ss,
    const float* __restrict__ b, float2* __restrict__ out)
{
    const int node = (blockIdx.x * blockDim.x + threadIdx.x) >> 5;
    const int lane = threadIdx.x & 31;

    int   col = 0;
    float att;
    if (lane < KNB) {
        col = ecol[node * KNB + lane];
        float ev = sd[node] + ss[col];
        att = (ev > 0.0f) ? ev : 0.2f * ev;     // leaky_relu slope 0.2
    } else {
        att = -1e30f;
    }

    float m = att;
    #pragma unroll
    for (int off = 8; off >= 1; off >>= 1)
        m = fmaxf(m, __shfl_xor_sync(0xffffffffu, m, off));
    const float ex = (lane < KNB) ? __expf(att - m) : 0.0f;
    float s = ex;
    #pragma unroll
    for (int off = 8; off >= 1; off >>= 1)
        s += __shfl_xor_sync(0xffffffffu, s, off);
    att = ex / s;                                // valid in lanes 0..15

    float2 acc = make_float2(0.f, 0.f);
    #pragma unroll
    for (int k = 0; k < KNB; k++) {
        const int   ck = __shfl_sync(0xffffffffu, col, k);
        const float ak = __shfl_sync(0xffffffffu, att, k);
        const float2 hv = __half22float2(hh[(size_t)ck * 32 + lane]);
        acc.x = fmaf(ak, hv.x, acc.x);
        acc.y = fmaf(ak, hv.y, acc.y);
    }

    const float2 bv = reinterpret_cast<const float2*>(b)[lane];
    acc.x = fmaxf(acc.x + bv.x, 0.0f);
    acc.y = fmaxf(acc.y + bv.y, 0.0f);
    out[(size_t)node * 32 + lane] = acc;
}

// ---------------------------------------------------------------------------
extern "C" void kernel_launch(void* const* d_in, const int* in_sizes, int n_in,
                              void* d_out, int out_size)
{
    const float* x    = (const float*)d_in[0];
    // d_in[1] = edge_row: exactly K per node, row-sorted -> implicit, unused
    const int*   ecol = (const int*)d_in[2];
    const float* W1   = (const float*)d_in[3];
    const float* a1   = (const float*)d_in[4];
    const float* b1   = (const float*)d_in[5];
    const float* W2   = (const float*)d_in[6];
    const float* a2   = (const float*)d_in[7];
    const float* b2   = (const float*)d_in[8];

    __half* h;  float *x1, *sd, *ss;
    cudaGetSymbolAddress((void**)&h,  g_h);
    cudaGetSymbolAddress((void**)&x1, g_x1);
    cudaGetSymbolAddress((void**)&sd, g_sd);
    cudaGetSymbolAddress((void**)&ss, g_ss);

    const int smem1 = (128 * 72 + 128 * 132) * 4;   // 102 KB
    const int smem2 = (64 * 72 + 128 * 68) * 4;     // 52 KB
    cudaFuncSetAttribute(gemm_mma_kernel<128>,
                         cudaFuncAttributeMaxDynamicSharedMemorySize, smem1);
    cudaFuncSetAttribute(gemm_mma_kernel<64>,
                         cudaFuncAttributeMaxDynamicSharedMemorySize, smem2);

    const int gemm_blocks = (NNODES + 127) / 128;   // 782
    const int agg_blocks  = NNODES / 8;             // 12500

    // Layer 1
    gemm_mma_kernel<128><<<gemm_blocks, 256, smem1>>>(x, W1, a1, h, sd, ss);
    agg_kernel<<<agg_blocks, 256>>>((const __half2*)h, ecol, sd, ss, b1,
                                    (float2*)x1);
    // Layer 2
    gemm_mma_kernel<64><<<gemm_blocks, 256, smem2>>>(x1, W2, a2, h, sd, ss);
    agg_kernel<<<agg_blocks, 256>>>((const __half2*)h, ecol, sd, ss, b2,
                                    (float2*)d_out);
}

// round 9
// speedup vs baseline: 1.6121x; 1.4121x over previous
#include <cuda_runtime.h>
#include <cuda_fp16.h>
#include <math.h>

#define NNODES 100000
#define KNB 16

// Scratch (bss, no allocation). h reused by both layers (sequential stream).
__device__ __align__(16) __half g_h[NNODES * 64];
__device__ __align__(16) float  g_x1[NNODES * 64];
__device__ float g_sd[NNODES];
__device__ float g_ss[NNODES];

// ---- helpers ---------------------------------------------------------------
__device__ __forceinline__ unsigned cvt_tf32(float f) {
    unsigned u;
    asm("cvt.rna.tf32.f32 %0, %1;" : "=r"(u) : "f"(f));
    return u;
}
__device__ __forceinline__ void mma_tf32(float* c,
    unsigned a0, unsigned a1, unsigned a2, unsigned a3,
    unsigned b0, unsigned b1)
{
    asm volatile(
        "mma.sync.aligned.m16n8k8.row.col.f32.tf32.tf32.f32 "
        "{%0,%1,%2,%3}, {%4,%5,%6,%7}, {%8,%9}, {%0,%1,%2,%3};"
        : "+f"(c[0]), "+f"(c[1]), "+f"(c[2]), "+f"(c[3])
        : "r"(a0), "r"(a1), "r"(a2), "r"(a3), "r"(b0), "r"(b1));
}
__device__ __forceinline__ unsigned smem_u32(const void* p) {
    unsigned a;
    asm("{ .reg .u64 t; cvta.to.shared.u64 t, %1; cvt.u32.u64 %0, t; }"
        : "=r"(a) : "l"(p));
    return a;
}
__device__ __forceinline__ void cp_async16(unsigned dst, const void* src, int sz) {
    asm volatile("cp.async.ca.shared.global [%0], [%1], 16, %2;"
                 :: "r"(dst), "l"(src), "r"(sz));
}
__device__ __forceinline__ unsigned long long pack2s(float lo, float hi) {
    unsigned long long r;
    asm("mov.b64 %0, {%1, %2};" : "=l"(r) : "f"(lo), "f"(hi));
    return r;
}
__device__ __forceinline__ unsigned long long pack2(float v) {
    unsigned long long r;
    asm("mov.b64 %0, {%1, %1};" : "=l"(r) : "f"(v));
    return r;
}
__device__ __forceinline__ void ffma2(unsigned long long& d,
                                      unsigned long long a,
                                      unsigned long long b) {
    asm("fma.rn.f32x2 %0, %1, %2, %0;" : "+l"(d) : "l"(a), "l"(b));
}
__device__ __forceinline__ float2 unpack2(unsigned long long v) {
    float2 f;
    asm("mov.b64 {%0, %1}, %2;" : "=f"(f.x), "=f"(f.y) : "l"(v));
    return f;
}

// ---------------------------------------------------------------------------
// GEMM h = x @ W (KD inner, 64 cols) on tf32 tensor cores + fused attention
// dots sd[i]=h[i].a[0:64], ss[i]=h[i].a[64:128]; h stored fp16.
// x tile is cp.async'd as RAW fp32 bits (tensor core truncates to tf32);
// the resulting -3.52e-4 relative truncation bias is cancelled by scaling W
// (rna-converted) with (1 + 3.52e-4) at fill time.
// Block: 256 threads, tile 128x64; warp w owns rows 16w..16w+15, all 64 cols.
// Padded strides keep fragment LDS conflict-free (xs: KD+4, Ws: 72).
// ---------------------------------------------------------------------------
template <int KD>
__global__ void __launch_bounds__(256) gemm_mma_kernel(
    const float* __restrict__ x, const float* __restrict__ W,
    const float* __restrict__ a, __half* __restrict__ h,
    float* __restrict__ sd, float* __restrict__ ss)
{
    constexpr int XS = KD + 4;   // padded x row stride (u32 units)
    constexpr int WS = 72;       // padded W row stride (u32 units)
    extern __shared__ unsigned smem_u[];
    unsigned* Wsu = smem_u;               // KD x WS   (tf32-rna, bias-comp)
    unsigned* xsu = smem_u + KD * WS;     // 128 x XS  (raw fp32 bits)

    const int tid  = threadIdx.x;
    const int warp = tid >> 5;
    const int lane = tid & 31;
    const int q = lane & 3;
    const int g = lane >> 2;
    const int rowbase = blockIdx.x * 128;

    // x tile: raw-bit async copy with zero-fill past the last valid row
    {
        constexpr int K4 = KD / 4;
        const float4* xg = reinterpret_cast<const float4*>(x + (size_t)rowbase * KD);
        const unsigned xsa = smem_u32(xsu);
        const int tot = 128 * K4;
        const int nvr = NNODES - rowbase;
        const int validv = (nvr >= 128) ? tot : nvr * K4;
        for (int i = tid; i < tot; i += 256) {
            const int r = i / K4, k4 = i % K4;
            const unsigned dst = xsa + (unsigned)(r * XS + k4 * 4) * 4u;
            const int sz = (i < validv) ? 16 : 0;
            cp_async16(dst, xg + (sz ? i : 0), sz);
        }
        asm volatile("cp.async.commit_group;");
    }
    // W tile: rna cvt + truncation-bias compensation (tiny: KD*64 elements)
    {
        const float comp = 1.000352f;   // 1 + E[trunc bias] of raw-bit A operand
        const float4* Wg = reinterpret_cast<const float4*>(W);
        #pragma unroll
        for (int i = tid; i < KD * 16; i += 256) {
            const float4 v = Wg[i];
            const int k = i >> 4, n4 = i & 15;
            uint4 u;
            u.x = cvt_tf32(v.x * comp); u.y = cvt_tf32(v.y * comp);
            u.z = cvt_tf32(v.z * comp); u.w = cvt_tf32(v.w * comp);
            *reinterpret_cast<uint4*>(&Wsu[k * WS + n4 * 4]) = u;
        }
    }
    asm volatile("cp.async.wait_group 0;");
    __syncthreads();

    float acc[8][4];
    #pragma unroll
    for (int nt = 0; nt < 8; nt++)
        #pragma unroll
        for (int j = 0; j < 4; j++) acc[nt][j] = 0.0f;

    const unsigned* xw = &xsu[(warp * 16) * XS];

    #pragma unroll
    for (int k0 = 0; k0 < KD; k0 += 8) {
        const unsigned a0 = xw[g * XS + k0 + q];
        const unsigned a1 = xw[(g + 8) * XS + k0 + q];
        const unsigned a2 = xw[g * XS + k0 + q + 4];
        const unsigned a3 = xw[(g + 8) * XS + k0 + q + 4];
        #pragma unroll
        for (int nt = 0; nt < 8; nt++) {
            const unsigned b0 = Wsu[(k0 + q) * WS + nt * 8 + g];
            const unsigned b1 = Wsu[(k0 + q + 4) * WS + nt * 8 + g];
            mma_tf32(acc[nt], a0, a1, a2, a3, b0, b1);
        }
    }

    // Fused attention dots. Thread owns rows (16w+g, 16w+g+8), cols {8nt+2q,+1}.
    float pd0 = 0.f, ps0 = 0.f, pd1 = 0.f, ps1 = 0.f;
    #pragma unroll
    for (int nt = 0; nt < 8; nt++) {
        const float2 av = reinterpret_cast<const float2*>(a)[nt * 4 + q];
        const float2 bv = reinterpret_cast<const float2*>(a + 64)[nt * 4 + q];
        pd0 += acc[nt][0] * av.x + acc[nt][1] * av.y;
        ps0 += acc[nt][0] * bv.x + acc[nt][1] * bv.y;
        pd1 += acc[nt][2] * av.x + acc[nt][3] * av.y;
        ps1 += acc[nt][2] * bv.x + acc[nt][3] * bv.y;
    }
    #pragma unroll
    for (int off = 2; off >= 1; off >>= 1) {
        pd0 += __shfl_xor_sync(0xffffffffu, pd0, off);
        ps0 += __shfl_xor_sync(0xffffffffu, ps0, off);
        pd1 += __shfl_xor_sync(0xffffffffu, pd1, off);
        ps1 += __shfl_xor_sync(0xffffffffu, ps1, off);
    }

    const int row0 = rowbase + warp * 16 + g;
    const int row1 = row0 + 8;
    if (q == 0) {
        if (row0 < NNODES) { sd[row0] = pd0; ss[row0] = ps0; }
        if (row1 < NNODES) { sd[row1] = pd1; ss[row1] = ps1; }
    }
    if (row0 < NNODES) {
        #pragma unroll
        for (int nt = 0; nt < 8; nt++) {
            const __half2 hv = __floats2half2_rn(acc[nt][0], acc[nt][1]);
            *reinterpret_cast<__half2*>(&h[(size_t)row0 * 64 + nt * 8 + 2 * q]) = hv;
        }
    }
    if (row1 < NNODES) {
        #pragma unroll
        for (int nt = 0; nt < 8; nt++) {
            const __half2 hv = __floats2half2_rn(acc[nt][2], acc[nt][3]);
            *reinterpret_cast<__half2*>(&h[(size_t)row1 * 64 + nt * 8 + 2 * q]) = hv;
        }
    }
}

// ---------------------------------------------------------------------------
// Attention softmax (K=16) + fp16 gather + bias + relu.  TWO nodes per warp:
// lanes 0-15 -> node 2w, lanes 16-31 -> node 2w+1. Each lane owns 4 feature
// cols (uint2 of 2 half2) -> LDG.64 touches exactly the 2 node rows (1 line
// each). Width-16 shuffles keep the halves independent.
// ---------------------------------------------------------------------------
__global__ void __launch_bounds__(256) agg_kernel(
    const uint2* __restrict__ hh, const int* __restrict__ ecol,
    const float* __restrict__ sd, const float* __restrict__ ss,
    const float* __restrict__ b, float4* __restrict__ out)
{
    const int warp = (blockIdx.x * blockDim.x + threadIdx.x) >> 5;
    const int lane = threadIdx.x & 31;
    const int l16  = lane & 15;
    const int node = warp * 2 + (lane >> 4);

    // ecol[node*16 + l16] == ecol[warp*32 + lane]  (coalesced)
    const int col = ecol[warp * 32 + lane];

    float ev = sd[node] + ss[col];
    ev = (ev > 0.0f) ? ev : 0.2f * ev;           // leaky_relu slope 0.2

    float m = ev;
    #pragma unroll
    for (int off = 8; off >= 1; off >>= 1)
        m = fmaxf(m, __shfl_xor_sync(0xffffffffu, m, off));
    const float ex = __expf(ev - m);
    float s = ex;
    #pragma unroll
    for (int off = 8; off >= 1; off >>= 1)
        s += __shfl_xor_sync(0xffffffffu, s, off);
    const float att = ex / s;

    unsigned long long accA = 0ull, accB = 0ull;   // f32x2 accumulators
    #pragma unroll
    for (int k = 0; k < KNB; k++) {
        const int   ck = __shfl_sync(0xffffffffu, col, k, 16);
        const float ak = __shfl_sync(0xffffffffu, att, k, 16);
        const uint2 hv = hh[(size_t)ck * 16 + l16];
        const float2 lo = __half22float2(*reinterpret_cast<const __half2*>(&hv.x));
        const float2 hi = __half22float2(*reinterpret_cast<const __half2*>(&hv.y));
        const unsigned long long pa = pack2(ak);
        ffma2(accA, pa, pack2s(lo.x, lo.y));
        ffma2(accB, pa, pack2s(hi.x, hi.y));
    }

    const float2 rA = unpack2(accA);
    const float2 rB = unpack2(accB);
    const float4 bv = reinterpret_cast<const float4*>(b)[l16];
    float4 o;
    o.x = fmaxf(rA.x + bv.x, 0.0f);
    o.y = fmaxf(rA.y + bv.y, 0.0f);
    o.z = fmaxf(rB.x + bv.z, 0.0f);
    o.w = fmaxf(rB.y + bv.w, 0.0f);
    out[(size_t)node * 16 + l16] = o;
}

// ---------------------------------------------------------------------------
extern "C" void kernel_launch(void* const* d_in, const int* in_sizes, int n_in,
                              void* d_out, int out_size)
{
    const float* x    = (const float*)d_in[0];
    // d_in[1] = edge_row: exactly K per node, row-sorted -> implicit, unused
    const int*   ecol = (const int*)d_in[2];
    const float* W1   = (const float*)d_in[3];
    const float* a1   = (const float*)d_in[4];
    const float* b1   = (const float*)d_in[5];
    const float* W2   = (const float*)d_in[6];
    const float* a2   = (const float*)d_in[7];
    const float* b2   = (const float*)d_in[8];

    __half* h;  float *x1, *sd, *ss;
    cudaGetSymbolAddress((void**)&h,  g_h);
    cudaGetSymbolAddress((void**)&x1, g_x1);
    cudaGetSymbolAddress((void**)&sd, g_sd);
    cudaGetSymbolAddress((void**)&ss, g_ss);

    const int smem1 = (128 * 72 + 128 * 132) * 4;   // ~102 KB
    const int smem2 = (64 * 72 + 128 * 68) * 4;     // ~52 KB
    cudaFuncSetAttribute(gemm_mma_kernel<128>,
                         cudaFuncAttributeMaxDynamicSharedMemorySize, smem1);
    cudaFuncSetAttribute(gemm_mma_kernel<64>,
                         cudaFuncAttributeMaxDynamicSharedMemorySize, smem2);

    const int gemm_blocks = (NNODES + 127) / 128;   // 782
    const int agg_blocks  = NNODES / 16;            // 6250 (8 warps x 2 nodes)

    // Layer 1
    gemm_mma_kernel<128><<<gemm_blocks, 256, smem1>>>(x, W1, a1, h, sd, ss);
    agg_kernel<<<agg_blocks, 256>>>((const uint2*)h, ecol, sd, ss, b1,
                                    (float4*)x1);
    // Layer 2
    gemm_mma_kernel<64><<<gemm_blocks, 256, smem2>>>(x1, W2, a2, h, sd, ss);
    agg_kernel<<<agg_blocks, 256>>>((const uint2*)h, ecol, sd, ss, b2,
                                    (float4*)d_out);
}